// round 12
// baseline (speedup 1.0000x reference)
#include <cuda_runtime.h>
#include <cuda_bf16.h>

#define BB 2
#define NN 1024
#define DD 16
#define HH 8
#define W1STRIDE (3 * DD + 1)   // 49

typedef unsigned long long ull;

// ---------------------------------------------------------------------------
// Constant-memory weight pack (constant-bank/uniform port, off the l1tex pipe)
// ---------------------------------------------------------------------------
struct ConstPack {
    ulonglong2 wd[3][HH][HH / 2];   // [l][h][kp]: ((w[2kp][h],)x2 , (w[2kp+1][h],)x2)
    ulonglong2 bd[3][HH / 2];
    ull        w5d[HH];
    ull        w1ad[HH];
    ull        b5d;
};
__constant__ ConstPack c_pack;
__device__   ConstPack g_stage;

__device__ __forceinline__ float tanh_approx(float x) {
    float y;
    asm("tanh.approx.f32 %0, %1;" : "=f"(y) : "f"(x));
    return y;
}
__device__ __forceinline__ ull pack2(float lo, float hi) {
    ull d;
    asm("mov.b64 %0, {%1, %2};" : "=l"(d) : "f"(lo), "f"(hi));
    return d;
}
__device__ __forceinline__ void unpack2(ull v, float& lo, float& hi) {
    asm("mov.b64 {%0, %1}, %2;" : "=f"(lo), "=f"(hi) : "l"(v));
}
__device__ __forceinline__ ull fma2(ull a, ull b, ull c) {
    ull d;
    asm("fma.rn.f32x2 %0, %1, %2, %3;" : "=l"(d) : "l"(a), "l"(b), "l"(c));
    return d;
}
__device__ __forceinline__ ull add2(ull a, ull b) {
    ull d;
    asm("add.rn.f32x2 %0, %1, %2;" : "=l"(d) : "l"(a), "l"(b));
    return d;
}
__device__ __forceinline__ ull tanh2(ull v) {
    float lo, hi;
    unpack2(v, lo, hi);
    return pack2(tanh_approx(lo), tanh_approx(hi));
}

// ---------------------------------------------------------------------------
// Prep kernel: pack duplicated-pair weight tables into the staging buffer.
// ---------------------------------------------------------------------------
__global__ void pack_kernel(const float* __restrict__ W1,
                            const float* __restrict__ W2, const float* __restrict__ b2,
                            const float* __restrict__ W3, const float* __restrict__ b3,
                            const float* __restrict__ W4, const float* __restrict__ b4,
                            const float* __restrict__ W5, const float* __restrict__ b5) {
    int t = threadIdx.x;
    if (t < 96) {                       // wd: 3 x 8 x 4
        int l  = t / 32;
        int h  = (t / 4) & 7;
        int kp = t & 3;
        const float* W = (l == 0) ? W2 : (l == 1) ? W3 : W4;
        float w0 = W[(2 * kp)     * HH + h];
        float w1 = W[(2 * kp + 1) * HH + h];
        g_stage.wd[l][h][kp] = make_ulonglong2(pack2(w0, w0), pack2(w1, w1));
    } else if (t < 108) {               // bd: 3 x 4
        int l  = (t - 96) / 4;
        int kp = (t - 96) & 3;
        const float* bb = (l == 0) ? b2 : (l == 1) ? b3 : b4;
        float v0 = bb[2 * kp], v1 = bb[2 * kp + 1];
        g_stage.bd[l][kp] = make_ulonglong2(pack2(v0, v0), pack2(v1, v1));
    } else if (t < 116) {               // w5d
        int h = t - 108;
        float w = W5[h];
        g_stage.w5d[h] = pack2(w, w);
    } else if (t < 124) {               // w1ad
        int h = t - 116;
        float w = W1[h * W1STRIDE + 3 * DD];
        g_stage.w1ad[h] = pack2(w, w);
    } else if (t == 124) {
        float v = b5[0];
        g_stage.b5d = pack2(v, v);
    }
}

// ---------------------------------------------------------------------------
// Main kernel: 512 threads, tile 32 i x 32 j, 2 edges/thread (one f32x2
// lane). Register-lean core (h2[8]+acc[8]) -> 2 CTAs of 512 = 32 warps/SM.
// All uniform weights from __constant__.
// ---------------------------------------------------------------------------
__global__ __launch_bounds__(512, 2)
void edge_mlp_kernel(const float* __restrict__ x,
                     const float* __restrict__ A,
                     const float* __restrict__ vp,
                     const float* __restrict__ W1, const float* __restrict__ b1,
                     float* __restrict__ out) {
    __shared__ __align__(16) float s_xj[32][DD];
    __shared__ __align__(16) float s_xi[32][DD];
    __shared__ __align__(16) float s_w1[HH * W1STRIDE];
    __shared__ __align__(16) float s_tjt[HH][32];   // t_j transposed [h][j]
    __shared__ __align__(16) float s_ti[32 * HH];   // t_i + t_v + b1, [i][h]

    const int tid = threadIdx.x;
    const int b  = blockIdx.z;
    const int i0 = blockIdx.y * 32;
    const int j0 = blockIdx.x * 32;

    // --- phase 1: stage x rows + W1 into shared ---
    {
        if (tid < 256) {
            int row = tid >> 2;            // 0..63
            int c4  = (tid & 3) * 4;
            if (row < 32) {
                float4 v = *reinterpret_cast<const float4*>(
                    x + ((size_t)(b * NN + j0 + row)) * DD + c4);
                s_xj[row][c4] = v.x; s_xj[row][c4 + 1] = v.y;
                s_xj[row][c4 + 2] = v.z; s_xj[row][c4 + 3] = v.w;
            } else {
                int r = row - 32;
                float4 v = *reinterpret_cast<const float4*>(
                    x + ((size_t)(b * NN + i0 + r)) * DD + c4);
                s_xi[r][c4] = v.x; s_xi[r][c4 + 1] = v.y;
                s_xi[r][c4 + 2] = v.z; s_xi[r][c4 + 3] = v.w;
            }
        } else {
            int g = tid - 256;             // 0..255
            if (g < HH * W1STRIDE - 256) s_w1[256 + g] = W1[256 + g];
            s_w1[g] = W1[g];
        }
    }
    __syncthreads();

    const int ii = tid >> 4;          // 0..31
    const int jl = (tid & 15) * 2;    // 0,2,...,30

    // Early global A load to overlap with phase 2
    const size_t off = ((size_t)(b * NN + i0 + ii)) * NN + j0 + jl;
    float2 a2f = *reinterpret_cast<const float2*>(A + off);

    // --- phase 2: projections, one (row,h) per thread (512 = 64 rows x 8 h) ---
    {
        int n = tid >> 3;      // 0..63
        int h = tid & 7;
        const float* wr = s_w1 + h * W1STRIDE;
        if (n < 32) {
            float tj = 0.0f;
#pragma unroll
            for (int c = 0; c < DD; c++)
                tj += s_xj[n][c] * wr[c];
            s_tjt[h][n] = tj;
        } else {
            int r = n - 32;
            float ti = 0.0f, tv = b1[h];
#pragma unroll
            for (int c = 0; c < DD; c++) {
                ti += s_xi[r][c] * wr[DD + c];
                tv += vp[b * DD + c] * wr[2 * DD + c];
            }
            s_ti[r * HH + h] = ti + tv;
        }
    }
    __syncthreads();

    // --- phase 3: packed edge MLP, one f32x2 lane (2 edges) ---
    ull av = pack2(a2f.x, a2f.y);

    // layer 1
    ull h2[HH];
#pragma unroll
    for (int h = 0; h < HH; h++) {
        ull tj2 = *reinterpret_cast<const ull*>(&s_tjt[h][jl]);
        float tival = s_ti[ii * HH + h];
        h2[h] = tanh2(fma2(av, c_pack.w1ad[h], add2(tj2, pack2(tival, tival))));
    }

    // layers 2..4: h outer, k inner; 8 independent acc chains
#pragma unroll
    for (int l = 0; l < 3; l++) {
        ull acc[HH];
#pragma unroll
        for (int kp = 0; kp < HH / 2; kp++) {
            ulonglong2 bk = c_pack.bd[l][kp];
            acc[kp * 2]     = bk.x;
            acc[kp * 2 + 1] = bk.y;
        }
#pragma unroll
        for (int h = 0; h < HH; h++) {
            ull hv = h2[h];
#pragma unroll
            for (int kp = 0; kp < HH / 2; kp++) {
                ulonglong2 w = c_pack.wd[l][h][kp];
                acc[kp * 2]     = fma2(hv, w.x, acc[kp * 2]);
                acc[kp * 2 + 1] = fma2(hv, w.y, acc[kp * 2 + 1]);
            }
        }
#pragma unroll
        for (int k = 0; k < HH; k++)
            h2[k] = tanh2(acc[k]);
    }

    // output layer
    ull o2 = c_pack.b5d;
#pragma unroll
    for (int h = 0; h < HH; h++)
        o2 = fma2(h2[h], c_pack.w5d[h], o2);
    float2 o;
    unpack2(o2, o.x, o.y);
    *reinterpret_cast<float2*>(out + off) = o;
}

// ---------------------------------------------------------------------------
extern "C" void kernel_launch(void* const* d_in, const int* in_sizes, int n_in,
                              void* d_out, int out_size) {
    const float* x  = (const float*)d_in[0];
    const float* A  = (const float*)d_in[1];
    const float* vp = (const float*)d_in[2];
    const float* W1 = (const float*)d_in[3];
    const float* b1 = (const float*)d_in[4];
    const float* W2 = (const float*)d_in[5];
    const float* b2 = (const float*)d_in[6];
    const float* W3 = (const float*)d_in[7];
    const float* b3 = (const float*)d_in[8];
    const float* W4 = (const float*)d_in[9];
    const float* b4 = (const float*)d_in[10];
    const float* W5 = (const float*)d_in[11];
    const float* b5 = (const float*)d_in[12];
    float* out = (float*)d_out;

    // 1) pack dup-pair tables into the staging buffer (device global)
    pack_kernel<<<1, 128>>>(W1, W2, b2, W3, b3, W4, b4, W5, b5);

    // 2) staging -> __constant__ as a plain D2D memcpy node (capture-safe)
    void* stage_ptr = nullptr;
    void* const_ptr = nullptr;
    cudaGetSymbolAddress(&stage_ptr, g_stage);
    cudaGetSymbolAddress(&const_ptr, c_pack);
    cudaMemcpyAsync(const_ptr, stage_ptr, sizeof(ConstPack),
                    cudaMemcpyDeviceToDevice, 0);

    // 3) main kernel
    dim3 grid(NN / 32, NN / 32, BB);   // 32 x 32 x 2 = 2048 blocks
    edge_mlp_kernel<<<grid, 512>>>(x, A, vp, W1, b1, out);
}